// round 1
// baseline (speedup 1.0000x reference)
#include <cuda_runtime.h>

#define NN 100000
#define EE 800000
#define ET (EE + NN)
#define GG 256
#define FD 128

// ------------------------- scratch (static device globals; no allocs) ------
__device__ float g_hpA[(size_t)NN * FD];   // GEMM output (per-layer transformed feats)
__device__ float g_hpB[(size_t)NN * FD];   // aggregate output (layer output)
__device__ float g_als[NN * 4];
__device__ float g_ald[NN * 4];
__device__ int   g_deg[NN];
__device__ int   g_rowptr[NN + 1];
__device__ int   g_cursor[NN];
__device__ int   g_csr[ET];
__device__ int   g_bsum[128];

// ------------------------------ CSR build ---------------------------------
__global__ void k_deg_init() {
    int i = blockIdx.x * blockDim.x + threadIdx.x;
    if (i < NN) g_deg[i] = 1;   // self-loop pre-counted
}

__global__ void k_count(const int* __restrict__ ei) {
    int e = blockIdx.x * blockDim.x + threadIdx.x;
    if (e < EE) atomicAdd(&g_deg[ei[EE + e]], 1);   // ei row 1 = dst
}

__global__ void k_scan1() {
    __shared__ int sh[1024];
    int tid = threadIdx.x;
    int i = blockIdx.x * 1024 + tid;
    int v = (i < NN) ? g_deg[i] : 0;
    sh[tid] = v;
    __syncthreads();
#pragma unroll
    for (int off = 1; off < 1024; off <<= 1) {
        int t = (tid >= off) ? sh[tid - off] : 0;
        __syncthreads();
        sh[tid] += t;
        __syncthreads();
    }
    if (i < NN) g_rowptr[i] = sh[tid] - v;          // exclusive
    if (tid == 1023) g_bsum[blockIdx.x] = sh[tid];  // block total
}

__global__ void k_scan2(int nb) {
    __shared__ int sh[128];
    int tid = threadIdx.x;
    sh[tid] = (tid < nb) ? g_bsum[tid] : 0;
    __syncthreads();
    if (tid == 0) {
        int run = 0;
        for (int i = 0; i < nb; i++) { int t = sh[i]; sh[i] = run; run += t; }
    }
    __syncthreads();
    if (tid < nb) g_bsum[tid] = sh[tid];
}

__global__ void k_scan3() {
    int i = blockIdx.x * blockDim.x + threadIdx.x;
    if (i < NN) {
        int r = g_rowptr[i] + g_bsum[i >> 10];
        g_rowptr[i] = r;
        g_cursor[i] = r;
    }
    if (i == 0) g_rowptr[NN] = ET;
}

__global__ void k_fill(const int* __restrict__ ei) {
    int t = blockIdx.x * blockDim.x + threadIdx.x;
    if (t < EE) {
        int s = ei[t], d = ei[EE + t];
        int slot = atomicAdd(&g_cursor[d], 1);
        g_csr[slot] = s;
    } else if (t < ET) {
        int n = t - EE;
        int slot = atomicAdd(&g_cursor[n], 1);
        g_csr[slot] = n;
    }
}

// make per-segment order deterministic (atomics fill in arbitrary order)
__global__ void k_sortseg() {
    int n = blockIdx.x * blockDim.x + threadIdx.x;
    if (n >= NN) return;
    int b = g_rowptr[n], e = g_rowptr[n + 1];
    for (int i = b + 1; i < e; i++) {
        int v = g_csr[i];
        int j = i - 1;
        while (j >= b && g_csr[j] > v) { g_csr[j + 1] = g_csr[j]; j--; }
        g_csr[j + 1] = v;
    }
}

// ------------------- GEMM: hp = A @ W^T  (+ fused logits) -----------------
// A: [NN, K], W: [128, K] row-major, hp: [NN, 128] (written to g_hpA)
// also writes g_als[n][h] = dot(hp[n, h*32:...], a_src[h]), same for a_dst.
template <int K>
__global__ void __launch_bounds__(256)
k_gemm(const float* __restrict__ Aext,
       const float* __restrict__ W,
       const float* __restrict__ asrc,
       const float* __restrict__ adst,
       int useExt) {
    __shared__ float sh_w[32][132];  // [kk][c], padded: conflict-free LDS.128
    __shared__ float sh_h[32][68];   // [kk][r], padded: 16B-aligned rows

    const float* __restrict__ A = useExt ? Aext : g_hpB;
    int tid = threadIdx.x;
    int tx = tid & 31, ty = tid >> 5;   // lane == tx (warp = fixed ty)
    int row0 = blockIdx.x * 64;

    float acc[8][4];
#pragma unroll
    for (int i = 0; i < 8; i++)
#pragma unroll
        for (int j = 0; j < 4; j++) acc[i][j] = 0.f;

    for (int k0 = 0; k0 < K; k0 += 32) {
#pragma unroll
        for (int idx = tid; idx < 4096; idx += 256) {
            int kk = idx & 31, c = idx >> 5;
            sh_w[kk][c] = W[c * K + k0 + kk];
        }
#pragma unroll
        for (int idx = tid; idx < 2048; idx += 256) {
            int kk = idx & 31, r = idx >> 5;
            int row = row0 + r;
            if (row >= NN) row = NN - 1;
            sh_h[kk][r] = A[(size_t)row * K + k0 + kk];
        }
        __syncthreads();
#pragma unroll
        for (int kk = 0; kk < 32; kk++) {
            float4 w4 = *(const float4*)&sh_w[kk][tx * 4];
            float4 h0 = *(const float4*)&sh_h[kk][ty * 8];
            float4 h1 = *(const float4*)&sh_h[kk][ty * 8 + 4];
            float hr[8] = {h0.x, h0.y, h0.z, h0.w, h1.x, h1.y, h1.z, h1.w};
#pragma unroll
            for (int i = 0; i < 8; i++) {
                acc[i][0] = fmaf(hr[i], w4.x, acc[i][0]);
                acc[i][1] = fmaf(hr[i], w4.y, acc[i][1]);
                acc[i][2] = fmaf(hr[i], w4.z, acc[i][2]);
                acc[i][3] = fmaf(hr[i], w4.w, acc[i][3]);
            }
        }
        __syncthreads();
    }

    // epilogue: store hp rows + fused attention logits (8-lane head groups)
    float4 as4 = *(const float4*)&asrc[tx * 4];
    float4 ad4 = *(const float4*)&adst[tx * 4];
    int h = tx >> 3;
#pragma unroll
    for (int i = 0; i < 8; i++) {
        int row = row0 + ty * 8 + i;
        float ps = acc[i][0] * as4.x + acc[i][1] * as4.y +
                   acc[i][2] * as4.z + acc[i][3] * as4.w;
        float pd = acc[i][0] * ad4.x + acc[i][1] * ad4.y +
                   acc[i][2] * ad4.z + acc[i][3] * ad4.w;
#pragma unroll
        for (int off = 4; off >= 1; off >>= 1) {
            ps += __shfl_xor_sync(0xffffffffu, ps, off);
            pd += __shfl_xor_sync(0xffffffffu, pd, off);
        }
        if (row < NN) {
            *(float4*)&g_hpA[(size_t)row * FD + tx * 4] =
                make_float4(acc[i][0], acc[i][1], acc[i][2], acc[i][3]);
            if ((tx & 7) == 0) {
                g_als[row * 4 + h] = ps;
                g_ald[row * 4 + h] = pd;
            }
        }
    }
}

// ----------- edge-softmax aggregation: one warp per dst node --------------
// reads g_hpA / g_als / g_ald / CSR; writes g_hpB = relu?(agg + bias)
__global__ void __launch_bounds__(256)
k_aggregate(const float* __restrict__ bias, int do_relu) {
    int n = (blockIdx.x * blockDim.x + threadIdx.x) >> 5;
    if (n >= NN) return;
    int lane = threadIdx.x & 31;
    int h = lane >> 3;                  // head for this lane's 4 channels
    int beg = g_rowptr[n], end = g_rowptr[n + 1];
    float ad = g_ald[n * 4 + h];

    float m = -1e30f, s = 0.f;
    float ax = 0.f, ay = 0.f, az = 0.f, aw = 0.f;

    for (int j = beg; j < end; j++) {
        int src = g_csr[j];
        float e = g_als[src * 4 + h] + ad;
        e = (e > 0.f) ? e : 0.2f * e;                 // leaky_relu 0.2
        float mn = fmaxf(m, e);
        float sc = __expf(m - mn);
        float p  = __expf(e - mn);
        float4 v = *(const float4*)&g_hpA[(size_t)src * FD + lane * 4];
        ax = ax * sc + p * v.x;
        ay = ay * sc + p * v.y;
        az = az * sc + p * v.z;
        aw = aw * sc + p * v.w;
        s = s * sc + p;
        m = mn;
    }
    float inv = 1.f / (s + 1e-16f);
    float4 b4 = *(const float4*)&bias[lane * 4];
    float ox = ax * inv + b4.x;
    float oy = ay * inv + b4.y;
    float oz = az * inv + b4.z;
    float ow = aw * inv + b4.w;
    if (do_relu) {
        ox = fmaxf(ox, 0.f); oy = fmaxf(oy, 0.f);
        oz = fmaxf(oz, 0.f); ow = fmaxf(ow, 0.f);
    }
    *(float4*)&g_hpB[(size_t)n * FD + lane * 4] = make_float4(ox, oy, oz, ow);
}

// -------------------- global mean pool (batch is sorted) ------------------
__device__ __forceinline__ int lowbound(const int* __restrict__ a, int n, int key) {
    int lo = 0, hi = n;
    while (lo < hi) {
        int mid = (lo + hi) >> 1;
        if (a[mid] < key) lo = mid + 1; else hi = mid;
    }
    return lo;
}

__global__ void k_pool(const int* __restrict__ batch, float* __restrict__ out) {
    __shared__ int sb, se;
    int g = blockIdx.x;
    if (threadIdx.x == 0) {
        sb = lowbound(batch, NN, g);
        se = lowbound(batch, NN, g + 1);
    }
    __syncthreads();
    int b = sb, e = se;
    float acc = 0.f;
    for (int nidx = b; nidx < e; nidx++)
        acc += g_hpB[(size_t)nidx * FD + threadIdx.x];
    float c = (float)(e - b);
    out[g * FD + threadIdx.x] = acc / fmaxf(c, 1.f);
}

// ------------------------------- driver -----------------------------------
extern "C" void kernel_launch(void* const* d_in, const int* in_sizes, int n_in,
                              void* d_out, int out_size) {
    const float* x     = (const float*)d_in[0];
    const int*   ei    = (const int*)d_in[1];
    // d_in[2] = edge_weight (unused by reference)
    const int*   batch = (const int*)d_in[3];
    const float* W0 = (const float*)d_in[4];
    const float* as0 = (const float*)d_in[5];
    const float* ad0 = (const float*)d_in[6];
    const float* b0 = (const float*)d_in[7];
    const float* W1 = (const float*)d_in[8];
    const float* as1 = (const float*)d_in[9];
    const float* ad1 = (const float*)d_in[10];
    const float* b1 = (const float*)d_in[11];
    const float* W2 = (const float*)d_in[12];
    const float* as2 = (const float*)d_in[13];
    const float* ad2 = (const float*)d_in[14];
    const float* b2 = (const float*)d_in[15];
    float* out = (float*)d_out;

    // --- CSR build (shared by all 3 layers) ---
    k_deg_init<<<(NN + 255) / 256, 256>>>();
    k_count<<<(EE + 255) / 256, 256>>>(ei);
    k_scan1<<<(NN + 1023) / 1024, 1024>>>();
    k_scan2<<<1, 128>>>((NN + 1023) / 1024);
    k_scan3<<<(NN + 255) / 256, 256>>>();
    k_fill<<<(ET + 255) / 256, 256>>>(ei);
    k_sortseg<<<(NN + 255) / 256, 256>>>();

    const int GEMM_GRID = (NN + 63) / 64;     // 1563
    const int AGG_GRID  = (NN * 32 + 255) / 256;  // 12500

    // layer 0: x(64) -> hpA -> aggregate(+b0, relu) -> hpB
    k_gemm<64><<<GEMM_GRID, 256>>>(x, W0, as0, ad0, 1);
    k_aggregate<<<AGG_GRID, 256>>>(b0, 1);
    // layer 1: hpB(128) -> hpA -> aggregate(+b1, relu) -> hpB
    k_gemm<128><<<GEMM_GRID, 256>>>(nullptr, W1, as1, ad1, 0);
    k_aggregate<<<AGG_GRID, 256>>>(b1, 1);
    // layer 2: hpB(128) -> hpA -> aggregate(+b2, no relu) -> hpB
    k_gemm<128><<<GEMM_GRID, 256>>>(nullptr, W2, as2, ad2, 0);
    k_aggregate<<<AGG_GRID, 256>>>(b2, 0);

    // global mean pool
    k_pool<<<GG, FD>>>(batch, out);
}